// round 9
// baseline (speedup 1.0000x reference)
#include <cuda_runtime.h>

typedef unsigned long long ull;
#define HST 132   // hq_s / hd_s row stride (16B-aligned, conflict-free)

// ---- f32x2 packed helpers ----
__device__ __forceinline__ ull pack2(float x, float y) {
    ull r; asm("mov.b64 %0, {%1,%2};" : "=l"(r) : "f"(x), "f"(y)); return r;
}
__device__ __forceinline__ void unpack2(ull v, float& x, float& y) {
    asm("mov.b64 {%0,%1}, %2;" : "=f"(x), "=f"(y) : "l"(v));
}
__device__ __forceinline__ ull fma2(ull a, ull b, ull c) {
    ull d; asm("fma.rn.f32x2 %0, %1, %2, %3;" : "=l"(d) : "l"(a), "l"(b), "l"(c)); return d;
}
__device__ __forceinline__ ull add2(ull a, ull b) {
    ull d; asm("add.rn.f32x2 %0, %1, %2;" : "=l"(d) : "l"(a), "l"(b)); return d;
}

// Mask dtype: 0 = int32, 1 = uint8, 2 = float32
__device__ __forceinline__ bool mask_at(const void* p, int i, int mode) {
    if (mode == 0) return ((const int*)p)[i] != 0;
    if (mode == 2) return ((const float*)p)[i] != 0.0f;
    return ((const unsigned char*)p)[i] != 0;
}

// ============================================================================
// grid = 128 = (batch, n-half). 512 threads (16 warps). 1 block/SM.
// Thin threads: hq 1 row x 8h, hd 2 rows x 8h, pair 1 tile/thread. 5 barriers.
// ============================================================================
__global__ void __launch_bounds__(512, 1)
fused_kernel(const float* __restrict__ query, const float* __restrict__ doc,
             const void* __restrict__ qmask, const void* __restrict__ dmask,
             const float* __restrict__ W1, const float* __restrict__ b1,
             const float* __restrict__ W2g, const float* __restrict__ b2g,
             float* __restrict__ out)
{
    extern __shared__ float sm[];
    float* Ws   = sm;                   // [128][128]  W1 half (q then d)
    float* Xq_s = Ws + 128 * 128;       // [32][128]
    float* Xd_s = Xq_s + 32 * 128;      // [64][128]
    float* hq_s = Xd_s + 64 * 128;      // [32][HST]
    float* hd_s = hq_s + 32 * HST;      // [64][HST]
    float* w2_s = hd_s + 64 * HST;      // [3][128]
    float* b1s  = w2_s + 384;           // [128]
    int* nlist  = (int*)(b1s + 128);    // 34 (local n in window)
    int* mlist  = nlist + 34;           // 66 (global m)
    int* meta   = mlist + 66;           // [0]=nvh [1]=mv

    const int tid  = threadIdx.x;
    const int lane = tid & 31;
    const int wid  = tid >> 5;
    const int b    = blockIdx.x >> 1;
    const int nh   = blockIdx.x & 1;

    // ---- zero-fill own 32n x 64m x 3 output window
    float* obase = out + (size_t)(b * 64 + nh * 32) * 192;
    {
        float4 z = make_float4(0.f, 0.f, 0.f, 0.f);
        for (int i = tid; i < 1536; i += 512) ((float4*)obase)[i] = z;
    }

    // ---- per-warp roles (no barrier needed before; meta read after barrier A)
    if (wid == 0 || wid == 1) {
        // in-warp dtype detection (no smem round-trip)
        const unsigned* qw = (const unsigned*)qmask;
        int notInt = 0, notF32 = 0;
        for (int i = lane; i < 512; i += 32) {
            unsigned w = qw[i];
            notInt |= (w > 1u) ? 1 : 0;
            notF32 |= (w != 0u && w != 0x3F800000u) ? 1 : 0;
        }
        notInt = __any_sync(0xFFFFFFFFu, notInt);
        notF32 = __any_sync(0xFFFFFFFFu, notF32);
        const int mode = (!notInt) ? 0 : ((!notF32) ? 2 : 1);
        const unsigned lt = (1u << lane) - 1u;

        if (wid == 0) {
            bool v = mask_at(qmask, b * 64 + nh * 32 + lane, mode);
            unsigned mm = __ballot_sync(0xFFFFFFFFu, v);
            if (v) nlist[__popc(mm & lt)] = lane;
            if (lane == 0) {
                int c = __popc(mm);
                meta[0] = c;
                if (c & 1) nlist[c] = 31 - __clz(mm);   // pad dup of last valid
            }
        } else {
            bool v0 = mask_at(dmask, b * 64 + lane, mode);
            unsigned m0 = __ballot_sync(0xFFFFFFFFu, v0);
            bool v1 = mask_at(dmask, b * 64 + 32 + lane, mode);
            unsigned m1 = __ballot_sync(0xFFFFFFFFu, v1);
            int c0 = __popc(m0);
            if (v0) mlist[__popc(m0 & lt)] = lane;
            if (v1) mlist[c0 + __popc(m1 & lt)] = 32 + lane;
            if (lane == 0) {
                int c = c0 + __popc(m1);
                meta[1] = c;
                if (c & 1) mlist[c] = m1 ? (32 + 31 - __clz(m1)) : (31 - __clz(m0));
            }
        }
    } else if (wid == 2 || wid == 3) {
        for (int i = tid - 64; i < 384; i += 64) {      // W2 (128,3) -> [o][h]
            int h = i / 3, o = i - h * 3;
            w2_s[o * 128 + h] = W2g[i];
        }
    } else if (wid == 4) {
        for (int i = lane; i < 128; i += 32) b1s[i] = b1[i];
    }
    // ---- stage W1 q-half (all threads): 4096 float4
    for (int i = tid; i < 4096; i += 512)
        *(float4*)(Ws + i * 4) = ((const float4*)W1)[i];
    __syncthreads();                                    // barrier A

    const int nvh = meta[0], mv = meta[1];
    const int nvhp = (nvh + 1) & ~1;
    const int mvp  = (mv + 1) & ~1;

    // ---- stage compacted Xq + Xd rows (lists ready)
    const float* Xq = query + (size_t)b * 8192;
    for (int i = tid; i < nvhp * 32; i += 512) {
        int r = i >> 5, seg = i & 31;
        *(float4*)(Xq_s + r * 128 + seg * 4) =
            ((const float4*)(Xq + (nh * 32 + nlist[r]) * 128))[seg];
    }
    const float* Xd = doc + (size_t)b * 8192;
    for (int i = tid; i < mvp * 32; i += 512) {
        int r = i >> 5, seg = i & 31;
        *(float4*)(Xd_s + r * 128 + seg * 4) =
            ((const float4*)(Xd + mlist[r] * 128))[seg];
    }
    __syncthreads();                                    // barrier B

    // thread h-mapping: 16 groups of 8h, bank-rotated 4-float chunks
    const int hgrp = tid & 15;
    const int h0   = hgrp * 8;
    const int cj   = (hgrp >> 2) & 1;
    const int o0   = h0 + 4 * cj;
    const int o1   = h0 + 4 * (cj ^ 1);
    const int prow = tid >> 4;            // 0..31

    // ---- hq: 1 row x 8h per thread (512 jobs)
    if (prow < nvhp) {
        ull a0 = 0, a1 = 0, a2 = 0, a3 = 0;
        const float* xb = Xq_s + prow * 128;
#pragma unroll 4
        for (int d = 0; d < 128; d++) {
            float x = xb[d];
            ull px = pack2(x, x);
            ulonglong2 wA = *(const ulonglong2*)(Ws + d * 128 + o0);
            ulonglong2 wB = *(const ulonglong2*)(Ws + d * 128 + o1);
            a0 = fma2(px, wA.x, a0); a1 = fma2(px, wA.y, a1);
            a2 = fma2(px, wB.x, a2); a3 = fma2(px, wB.y, a3);
        }
        float4 bA = *(const float4*)(b1s + o0);
        float4 bB = *(const float4*)(b1s + o1);
        float v0, v1, v2, v3;
        unpack2(a0, v0, v1); unpack2(a1, v2, v3);
        *(float4*)(hq_s + prow * HST + o0) =
            make_float4(v0 + bA.x, v1 + bA.y, v2 + bA.z, v3 + bA.w);
        unpack2(a2, v0, v1); unpack2(a3, v2, v3);
        *(float4*)(hq_s + prow * HST + o1) =
            make_float4(v0 + bB.x, v1 + bB.y, v2 + bB.z, v3 + bB.w);
    }
    __syncthreads();                                    // barrier C

    // ---- restage W1 d-half
    for (int i = tid; i < 4096; i += 512)
        *(float4*)(Ws + i * 4) = ((const float4*)(W1 + 16384))[i];
    __syncthreads();                                    // barrier D

    // ---- hd: 2 rows (r, r+32) x 8h per thread
    {
        const int r0 = prow, r1 = prow + 32;
        const bool g0 = r0 < mvp, g1 = r1 < mvp;
        if (g0) {
            ull a0=0, a1=0, a2=0, a3=0, a4=0, a5=0, a6=0, a7=0;
            const float* x0 = Xd_s + r0 * 128;
            const float* x1 = Xd_s + r1 * 128;
#pragma unroll 4
            for (int d = 0; d < 128; d++) {
                ulonglong2 wA = *(const ulonglong2*)(Ws + d * 128 + o0);
                ulonglong2 wB = *(const ulonglong2*)(Ws + d * 128 + o1);
                float xa = x0[d];
                ull pa = pack2(xa, xa);
                a0 = fma2(pa, wA.x, a0); a1 = fma2(pa, wA.y, a1);
                a2 = fma2(pa, wB.x, a2); a3 = fma2(pa, wB.y, a3);
                if (g1) {
                    float xc = x1[d];
                    ull pc = pack2(xc, xc);
                    a4 = fma2(pc, wA.x, a4); a5 = fma2(pc, wA.y, a5);
                    a6 = fma2(pc, wB.x, a6); a7 = fma2(pc, wB.y, a7);
                }
            }
            float v0, v1, v2, v3;
            unpack2(a0, v0, v1); unpack2(a1, v2, v3);
            *(float4*)(hd_s + r0 * HST + o0) = make_float4(v0, v1, v2, v3);
            unpack2(a2, v0, v1); unpack2(a3, v2, v3);
            *(float4*)(hd_s + r0 * HST + o1) = make_float4(v0, v1, v2, v3);
            if (g1) {
                unpack2(a4, v0, v1); unpack2(a5, v2, v3);
                *(float4*)(hd_s + r1 * HST + o0) = make_float4(v0, v1, v2, v3);
                unpack2(a6, v0, v1); unpack2(a7, v2, v3);
                *(float4*)(hd_s + r1 * HST + o1) = make_float4(v0, v1, v2, v3);
            }
        }
    }
    __syncthreads();                                    // barrier E

    // ---- pairwise: <=512 2x2 tiles, 1 per thread, rows paired (i, i+count/2)
    const int nt = nvhp >> 1, mt = mvp >> 1;
    const int total = nt * mt;
    if (tid < total) {
        const int ni = tid / mt;
        const int mi = tid - ni * mt;
        const float* pa0 = hq_s + ni * HST;
        const float* pa1 = hq_s + (ni + nt) * HST;
        const float* pd0 = hd_s + mi * HST;
        const float* pd1 = hd_s + (mi + mt) * HST;
        const float b2_0 = b2g[0], b2_1 = b2g[1], b2_2 = b2g[2];

        ull acc[4][3];
#pragma unroll
        for (int c = 0; c < 4; c++)
#pragma unroll
            for (int o = 0; o < 3; o++) acc[c][o] = 0ull;

#define COMBO(c, Alo, Ahi, Dlo, Dhi) do {                                   \
            ull tlo = add2((Alo), (Dlo));                                    \
            ull thi = add2((Ahi), (Dhi));                                    \
            float f0, f1, f2, f3;                                            \
            unpack2(tlo, f0, f1); unpack2(thi, f2, f3);                      \
            f0 = fmaxf(f0, 0.f); f1 = fmaxf(f1, 0.f);                        \
            f2 = fmaxf(f2, 0.f); f3 = fmaxf(f3, 0.f);                        \
            tlo = pack2(f0, f1); thi = pack2(f2, f3);                        \
            acc[c][0] = fma2(tlo, w0.x, acc[c][0]);                          \
            acc[c][0] = fma2(thi, w0.y, acc[c][0]);                          \
            acc[c][1] = fma2(tlo, w1.x, acc[c][1]);                          \
            acc[c][1] = fma2(thi, w1.y, acc[c][1]);                          \
            acc[c][2] = fma2(tlo, w2v.x, acc[c][2]);                         \
            acc[c][2] = fma2(thi, w2v.y, acc[c][2]);                         \
        } while (0)

#pragma unroll 4
        for (int h = 0; h < 128; h += 4) {
            ulonglong2 A0 = *(const ulonglong2*)(pa0 + h);
            ulonglong2 A1 = *(const ulonglong2*)(pa1 + h);
            ulonglong2 D0 = *(const ulonglong2*)(pd0 + h);
            ulonglong2 D1 = *(const ulonglong2*)(pd1 + h);
            ulonglong2 w0  = *(const ulonglong2*)(w2_s + h);
            ulonglong2 w1  = *(const ulonglong2*)(w2_s + 128 + h);
            ulonglong2 w2v = *(const ulonglong2*)(w2_s + 256 + h);
            COMBO(0, A0.x, A0.y, D0.x, D0.y);
            COMBO(1, A0.x, A0.y, D1.x, D1.y);
            COMBO(2, A1.x, A1.y, D0.x, D0.y);
            COMBO(3, A1.x, A1.y, D1.x, D1.y);
        }
#undef COMBO

        const int gn0 = nlist[ni], gn1 = nlist[ni + nt];
        const int gm0 = mlist[mi], gm1 = mlist[mi + mt];

#define WRITE(c, gn, gm) do {                                               \
            float lo, hi, s0, s1, s2;                                        \
            unpack2(acc[c][0], lo, hi); s0 = lo + hi + b2_0;                 \
            unpack2(acc[c][1], lo, hi); s1 = lo + hi + b2_1;                 \
            unpack2(acc[c][2], lo, hi); s2 = lo + hi + b2_2;                 \
            float* po = obase + (gn) * 192 + (gm) * 3;                       \
            po[0] = s0; po[1] = s1; po[2] = s2;                              \
        } while (0)

        WRITE(0, gn0, gm0);
        WRITE(1, gn0, gm1);
        WRITE(2, gn1, gm0);
        WRITE(3, gn1, gm1);
#undef WRITE
    }
}

// ============================================================================
extern "C" void kernel_launch(void* const* d_in, const int* in_sizes, int n_in,
                              void* d_out, int out_size)
{
    const float* query = (const float*)d_in[0];
    const float* doc   = (const float*)d_in[1];
    const void*  qmask = d_in[2];
    const void*  dmask = d_in[3];
    const float* W1    = (const float*)d_in[4];
    const float* b1    = (const float*)d_in[5];
    const float* W2    = (const float*)d_in[6];
    const float* b2    = (const float*)d_in[7];
    float* out = (float*)d_out;

    const int smem = (128 * 128 + 32 * 128 + 64 * 128 + 32 * HST + 64 * HST
                      + 384 + 128) * (int)sizeof(float)
                     + (34 + 66 + 2) * (int)sizeof(int);   // ~166 KB

    cudaFuncSetAttribute(fused_kernel,
                         cudaFuncAttributeMaxDynamicSharedMemorySize, smem);

    fused_kernel<<<128, 512, smem>>>(query, doc, qmask, dmask, W1, b1, W2, b2, out);
}

// round 10
// speedup vs baseline: 1.1996x; 1.1996x over previous
#include <cuda_runtime.h>

typedef unsigned long long ull;
#define HST 132   // row stride for Xq_s/Xd_s/hq_s/hd_s (conflict-free .128)

// ---- f32x2 packed helpers ----
__device__ __forceinline__ ull pack2(float x, float y) {
    ull r; asm("mov.b64 %0, {%1,%2};" : "=l"(r) : "f"(x), "f"(y)); return r;
}
__device__ __forceinline__ void unpack2(ull v, float& x, float& y) {
    asm("mov.b64 {%0,%1}, %2;" : "=f"(x), "=f"(y) : "l"(v));
}
__device__ __forceinline__ ull fma2(ull a, ull b, ull c) {
    ull d; asm("fma.rn.f32x2 %0, %1, %2, %3;" : "=l"(d) : "l"(a), "l"(b), "l"(c)); return d;
}
__device__ __forceinline__ ull add2(ull a, ull b) {
    ull d; asm("add.rn.f32x2 %0, %1, %2;" : "=l"(d) : "l"(a), "l"(b)); return d;
}

// Mask dtype: 0 = int32, 1 = uint8, 2 = float32
__device__ __forceinline__ bool mask_at(const void* p, int i, int mode) {
    if (mode == 0) return ((const int*)p)[i] != 0;
    if (mode == 2) return ((const float*)p)[i] != 0.0f;
    return ((const unsigned char*)p)[i] != 0;
}

// One proj job body: this lane computes 1 row x 8 h over all 128 d.
// W loads are warp-near-uniform (2 distinct 16B addrs -> 1 wavefront).
__device__ __forceinline__ void proj_body(const float* __restrict__ xr,
                                          const float* __restrict__ wc,
                                          bool store, float* dst,
                                          const float* bias)
{
    ull a0 = 0, a1 = 0, a2 = 0, a3 = 0;
#pragma unroll 4
    for (int d4 = 0; d4 < 32; d4++) {
        float4 x4 = *(const float4*)(xr + 4 * d4);
        const float* wp = wc + d4 * 512;
        float xs[4] = {x4.x, x4.y, x4.z, x4.w};
#pragma unroll
        for (int k = 0; k < 4; k++) {
            ull px = pack2(xs[k], xs[k]);
            ulonglong2 wA = *(const ulonglong2*)(wp + k * 128);
            ulonglong2 wB = *(const ulonglong2*)(wp + k * 128 + 4);
            a0 = fma2(px, wA.x, a0); a1 = fma2(px, wA.y, a1);
            a2 = fma2(px, wB.x, a2); a3 = fma2(px, wB.y, a3);
        }
    }
    if (store) {
        float v0, v1, v2, v3;
        if (bias) {
            float4 bA = *(const float4*)(bias);
            float4 bB = *(const float4*)(bias + 4);
            unpack2(a0, v0, v1); unpack2(a1, v2, v3);
            *(float4*)dst = make_float4(v0 + bA.x, v1 + bA.y, v2 + bA.z, v3 + bA.w);
            unpack2(a2, v0, v1); unpack2(a3, v2, v3);
            *(float4*)(dst + 4) = make_float4(v0 + bB.x, v1 + bB.y, v2 + bB.z, v3 + bB.w);
        } else {
            unpack2(a0, v0, v1); unpack2(a1, v2, v3);
            *(float4*)dst = make_float4(v0, v1, v2, v3);
            unpack2(a2, v0, v1); unpack2(a3, v2, v3);
            *(float4*)(dst + 4) = make_float4(v0, v1, v2, v3);
        }
    }
}

// ============================================================================
// grid = 128 = (batch, n-half). 512 threads (16 warps). 1 block/SM.
// Proj warp-job = 16 rows x 16 h (lane = 1 row x 8 h): W broadcast loads,
// warp-uniform mask skipping at 16-row-group granularity.
// ============================================================================
__global__ void __launch_bounds__(512, 1)
fused_kernel(const float* __restrict__ query, const float* __restrict__ doc,
             const void* __restrict__ qmask, const void* __restrict__ dmask,
             const float* __restrict__ W1, const float* __restrict__ b1,
             const float* __restrict__ W2g, const float* __restrict__ b2g,
             float* __restrict__ out)
{
    extern __shared__ float sm[];
    float* Ws   = sm;                   // [128][128]  W1 half (q then d)
    float* Xq_s = Ws + 16384;           // [32][HST]
    float* Xd_s = Xq_s + 32 * HST;      // [64][HST]
    float* hq_s = Xd_s + 64 * HST;      // [32][HST]
    float* hd_s = hq_s + 32 * HST;      // [64][HST]
    float* w2_s = hd_s + 64 * HST;      // [3][128]
    float* b1s  = w2_s + 384;           // [128]
    int* nlist  = (int*)(b1s + 128);    // 34 (local n in window)
    int* mlist  = nlist + 34;           // 66 (global m)
    int* meta   = mlist + 66;           // [0]=nvh [1]=mv

    const int tid  = threadIdx.x;
    const int lane = tid & 31;
    const int wid  = tid >> 5;
    const int b    = blockIdx.x >> 1;
    const int nh   = blockIdx.x & 1;

    // ---- zero-fill own 32n x 64m x 3 output window
    float* obase = out + (size_t)(b * 64 + nh * 32) * 192;
    {
        float4 z = make_float4(0.f, 0.f, 0.f, 0.f);
        for (int i = tid; i < 1536; i += 512) ((float4*)obase)[i] = z;
    }

    // ---- per-warp roles
    if (wid == 0 || wid == 1) {
        const unsigned* qw = (const unsigned*)qmask;
        int notInt = 0, notF32 = 0;
        for (int i = lane; i < 512; i += 32) {
            unsigned w = qw[i];
            notInt |= (w > 1u) ? 1 : 0;
            notF32 |= (w != 0u && w != 0x3F800000u) ? 1 : 0;
        }
        notInt = __any_sync(0xFFFFFFFFu, notInt);
        notF32 = __any_sync(0xFFFFFFFFu, notF32);
        const int mode = (!notInt) ? 0 : ((!notF32) ? 2 : 1);
        const unsigned lt = (1u << lane) - 1u;

        if (wid == 0) {
            bool v = mask_at(qmask, b * 64 + nh * 32 + lane, mode);
            unsigned mm = __ballot_sync(0xFFFFFFFFu, v);
            if (v) nlist[__popc(mm & lt)] = lane;
            if (lane == 0) {
                int c = __popc(mm);
                meta[0] = c;
                if (c & 1) nlist[c] = 31 - __clz(mm);   // pad dup of last
            }
        } else {
            bool v0 = mask_at(dmask, b * 64 + lane, mode);
            unsigned m0 = __ballot_sync(0xFFFFFFFFu, v0);
            bool v1 = mask_at(dmask, b * 64 + 32 + lane, mode);
            unsigned m1 = __ballot_sync(0xFFFFFFFFu, v1);
            int c0 = __popc(m0);
            if (v0) mlist[__popc(m0 & lt)] = lane;
            if (v1) mlist[c0 + __popc(m1 & lt)] = 32 + lane;
            if (lane == 0) {
                int c = c0 + __popc(m1);
                meta[1] = c;
                if (c & 1) mlist[c] = m1 ? (32 + 31 - __clz(m1)) : (31 - __clz(m0));
            }
        }
    } else if (wid == 2 || wid == 3) {
        for (int i = tid - 64; i < 384; i += 64) {      // W2 (128,3) -> [o][h]
            int h = i / 3, o = i - h * 3;
            w2_s[o * 128 + h] = W2g[i];
        }
    } else if (wid == 4) {
        for (int i = lane; i < 128; i += 32) b1s[i] = b1[i];
    }
    // ---- stage W1 q-half (all threads)
    for (int i = tid; i < 4096; i += 512)
        *(float4*)(Ws + i * 4) = ((const float4*)W1)[i];
    __syncthreads();                                    // A

    const int nvh = meta[0], mv = meta[1];
    const int nvhp = (nvh + 1) & ~1;
    const int mvp  = (mv + 1) & ~1;

    // ---- stage compacted Xq + Xd rows (float4, conflict-free)
    const float* Xq = query + (size_t)b * 8192;
    for (int i = tid; i < nvhp * 32; i += 512) {
        int r = i >> 5, seg = i & 31;
        *(float4*)(Xq_s + r * HST + seg * 4) =
            ((const float4*)(Xq + (nh * 32 + nlist[r]) * 128))[seg];
    }
    const float* Xd = doc + (size_t)b * 8192;
    for (int i = tid; i < mvp * 32; i += 512) {
        int r = i >> 5, seg = i & 31;
        *(float4*)(Xd_s + r * HST + seg * 4) =
            ((const float4*)(Xd + mlist[r] * 128))[seg];
    }
    __syncthreads();                                    // B

    const int lrow = lane & 15;
    const int hsub = lane >> 4;

    // ---- hq: warp job = (rowgroup, h-slice); 2 rowgroups x 8 slices = 16 jobs
    {
        const int rg = wid >> 3, hs = wid & 7;
        if (rg * 16 < nvhp) {
            const int r0 = rg * 16 + lrow;
            const int h0 = hs * 16 + hsub * 8;
            proj_body(Xq_s + r0 * HST, Ws + h0,
                      r0 < nvhp, hq_s + r0 * HST + h0, b1s + h0);
        }
    }
    __syncthreads();                                    // C

    // ---- restage W1 d-half
    for (int i = tid; i < 4096; i += 512)
        *(float4*)(Ws + i * 4) = ((const float4*)(W1 + 16384))[i];
    __syncthreads();                                    // D

    // ---- hd: 4 rowgroups x 8 slices = 32 jobs; warp does wid, wid+16
#pragma unroll
    for (int j0 = 0; j0 < 2; j0++) {
        const int j  = wid + j0 * 16;
        const int rg = j >> 3, hs = j & 7;
        if (rg * 16 < mvp) {
            const int r0 = rg * 16 + lrow;
            const int h0 = hs * 16 + hsub * 8;
            proj_body(Xd_s + r0 * HST, Ws + h0,
                      r0 < mvp, hd_s + r0 * HST + h0, (const float*)0);
        }
    }
    __syncthreads();                                    // E

    // ---- pairwise: <=512 2x2 tiles, 1/thread; lanes share ni -> A broadcast
    const int nt = nvhp >> 1, mt = mvp >> 1;
    const int total = nt * mt;
    if (tid < total) {
        const int ni = tid / mt;
        const int mi = tid - ni * mt;
        const float* pa0 = hq_s + ni * HST;
        const float* pa1 = hq_s + (ni + nt) * HST;
        const float* pd0 = hd_s + mi * HST;
        const float* pd1 = hd_s + (mi + mt) * HST;
        const float b2_0 = b2g[0], b2_1 = b2g[1], b2_2 = b2g[2];

        ull acc[4][3];
#pragma unroll
        for (int c = 0; c < 4; c++)
#pragma unroll
            for (int o = 0; o < 3; o++) acc[c][o] = 0ull;

#define COMBO(c, Alo, Ahi, Dlo, Dhi) do {                                   \
            ull tlo = add2((Alo), (Dlo));                                    \
            ull thi = add2((Ahi), (Dhi));                                    \
            float f0, f1, f2, f3;                                            \
            unpack2(tlo, f0, f1); unpack2(thi, f2, f3);                      \
            f0 = fmaxf(f0, 0.f); f1 = fmaxf(f1, 0.f);                        \
            f2 = fmaxf(f2, 0.f); f3 = fmaxf(f3, 0.f);                        \
            tlo = pack2(f0, f1); thi = pack2(f2, f3);                        \
            acc[c][0] = fma2(tlo, w0.x, acc[c][0]);                          \
            acc[c][0] = fma2(thi, w0.y, acc[c][0]);                          \
            acc[c][1] = fma2(tlo, w1.x, acc[c][1]);                          \
            acc[c][1] = fma2(thi, w1.y, acc[c][1]);                          \
            acc[c][2] = fma2(tlo, w2v.x, acc[c][2]);                         \
            acc[c][2] = fma2(thi, w2v.y, acc[c][2]);                         \
        } while (0)

#pragma unroll 4
        for (int h = 0; h < 128; h += 4) {
            ulonglong2 A0 = *(const ulonglong2*)(pa0 + h);
            ulonglong2 A1 = *(const ulonglong2*)(pa1 + h);
            ulonglong2 D0 = *(const ulonglong2*)(pd0 + h);
            ulonglong2 D1 = *(const ulonglong2*)(pd1 + h);
            ulonglong2 w0  = *(const ulonglong2*)(w2_s + h);
            ulonglong2 w1  = *(const ulonglong2*)(w2_s + 128 + h);
            ulonglong2 w2v = *(const ulonglong2*)(w2_s + 256 + h);
            COMBO(0, A0.x, A0.y, D0.x, D0.y);
            COMBO(1, A0.x, A0.y, D1.x, D1.y);
            COMBO(2, A1.x, A1.y, D0.x, D0.y);
            COMBO(3, A1.x, A1.y, D1.x, D1.y);
        }
#undef COMBO

        const int gn0 = nlist[ni], gn1 = nlist[ni + nt];
        const int gm0 = mlist[mi], gm1 = mlist[mi + mt];

#define WRITE(c, gn, gm) do {                                               \
            float lo, hi, s0, s1, s2;                                        \
            unpack2(acc[c][0], lo, hi); s0 = lo + hi + b2_0;                 \
            unpack2(acc[c][1], lo, hi); s1 = lo + hi + b2_1;                 \
            unpack2(acc[c][2], lo, hi); s2 = lo + hi + b2_2;                 \
            float* po = obase + (gn) * 192 + (gm) * 3;                       \
            po[0] = s0; po[1] = s1; po[2] = s2;                              \
        } while (0)

        WRITE(0, gn0, gm0);
        WRITE(1, gn0, gm1);
        WRITE(2, gn1, gm0);
        WRITE(3, gn1, gm1);
#undef WRITE
    }
}

// ============================================================================
extern "C" void kernel_launch(void* const* d_in, const int* in_sizes, int n_in,
                              void* d_out, int out_size)
{
    const float* query = (const float*)d_in[0];
    const float* doc   = (const float*)d_in[1];
    const void*  qmask = d_in[2];
    const void*  dmask = d_in[3];
    const float* W1    = (const float*)d_in[4];
    const float* b1    = (const float*)d_in[5];
    const float* W2    = (const float*)d_in[6];
    const float* b2    = (const float*)d_in[7];
    float* out = (float*)d_out;

    const int smem = (16384 + 32 * HST + 64 * HST + 32 * HST + 64 * HST
                      + 384 + 128) * (int)sizeof(float)
                     + (34 + 66 + 2) * (int)sizeof(int);   // ~170 KB

    cudaFuncSetAttribute(fused_kernel,
                         cudaFuncAttributeMaxDynamicSharedMemorySize, smem);

    fused_kernel<<<128, 512, smem>>>(query, doc, qmask, dmask, W1, b1, W2, b2, out);
}

// round 11
// speedup vs baseline: 1.2571x; 1.0479x over previous
#include <cuda_runtime.h>

typedef unsigned long long ull;
#define HST 132   // smem row stride for X / hq / hd (conflict-free .128)

__device__ float g_hq[64 * 64 * 128];   // [b][j][h], j = compacted valid-n index
__device__ float g_hd[64 * 64 * 128];   // [b][j][h], j = compacted valid-m index

// ---- f32x2 packed helpers ----
__device__ __forceinline__ ull pack2(float x, float y) {
    ull r; asm("mov.b64 %0, {%1,%2};" : "=l"(r) : "f"(x), "f"(y)); return r;
}
__device__ __forceinline__ void unpack2(ull v, float& x, float& y) {
    asm("mov.b64 {%0,%1}, %2;" : "=f"(x), "=f"(y) : "l"(v));
}
__device__ __forceinline__ ull fma2(ull a, ull b, ull c) {
    ull d; asm("fma.rn.f32x2 %0, %1, %2, %3;" : "=l"(d) : "l"(a), "l"(b), "l"(c)); return d;
}
__device__ __forceinline__ ull add2(ull a, ull b) {
    ull d; asm("add.rn.f32x2 %0, %1, %2;" : "=l"(d) : "l"(a), "l"(b)); return d;
}

// Mask dtype: 0 = int32, 1 = uint8, 2 = float32
__device__ __forceinline__ bool mask_at(const void* p, int i, int mode) {
    if (mode == 0) return ((const int*)p)[i] != 0;
    if (mode == 2) return ((const float*)p)[i] != 0.0f;
    return ((const unsigned char*)p)[i] != 0;
}

// In-warp mask dtype detection (registers only)
__device__ __forceinline__ int detect_mode(const void* qmask, int lane) {
    const unsigned* qw = (const unsigned*)qmask;
    int notInt = 0, notF32 = 0;
    for (int i = lane; i < 512; i += 32) {
        unsigned w = qw[i];
        notInt |= (w > 1u) ? 1 : 0;
        notF32 |= (w != 0u && w != 0x3F800000u) ? 1 : 0;
    }
    notInt = __any_sync(0xFFFFFFFFu, notInt);
    notF32 = __any_sync(0xFFFFFFFFu, notF32);
    return (!notInt) ? 0 : ((!notF32) ? 2 : 1);
}

// ============================================================================
// Proj: grid = 512 = (b, side, hslice32). 256 threads, ~50KB smem, 4 blk/SM.
// Computes compacted h-rows for a 32-wide h slice; broadcast-W warp mapping.
// ============================================================================
__global__ void __launch_bounds__(256)
proj_kernel(const float* __restrict__ query, const float* __restrict__ doc,
            const void* __restrict__ qmask, const void* __restrict__ dmask,
            const float* __restrict__ W1, const float* __restrict__ b1)
{
    extern __shared__ float sm[];
    float* Wsl = sm;                    // [128][32]  W1 slice
    float* Xs  = Wsl + 128 * 32;        // [64][HST]
    float* b1s = Xs + 64 * HST;         // [32]
    int* list  = (int*)(b1s + 32);      // 64
    int* meta  = list + 64;             // [0]=cnt

    const int tid  = threadIdx.x;
    const int lane = tid & 31;
    const int wid  = tid >> 5;
    const int b    = blockIdx.x >> 3;
    const int side = (blockIdx.x >> 2) & 1;
    const int hs4  = blockIdx.x & 3;    // 32-h slice

    if (wid == 0) {
        const int mode = detect_mode(qmask, lane);
        const void* mp = side ? dmask : qmask;
        const unsigned lt = (1u << lane) - 1u;
        bool v0 = mask_at(mp, b * 64 + lane, mode);
        unsigned m0 = __ballot_sync(0xFFFFFFFFu, v0);
        bool v1 = mask_at(mp, b * 64 + 32 + lane, mode);
        unsigned m1 = __ballot_sync(0xFFFFFFFFu, v1);
        int c0 = __popc(m0);
        if (v0) list[__popc(m0 & lt)] = lane;
        if (v1) list[c0 + __popc(m1 & lt)] = 32 + lane;
        if (lane == 0) meta[0] = c0 + __popc(m1);
        b1s[lane] = (side == 0) ? b1[hs4 * 32 + lane] : 0.0f;
    } else {
        // stage W1 slice: rows d 0..127, cols hs4*32..+32  (1024 float4)
        const float* Wg = W1 + side * 16384 + hs4 * 32;
        for (int i = tid - 32; i < 1024; i += 224) {
            int d = i >> 3, c4 = i & 7;
            *(float4*)(Wsl + d * 32 + c4 * 4) = *(const float4*)(Wg + d * 128 + c4 * 4);
        }
    }
    __syncthreads();

    const int cnt = meta[0];
    if (cnt == 0) return;

    // stage compacted X rows
    const float* X = (side ? doc : query) + (size_t)b * 8192;
    for (int i = tid; i < cnt * 32; i += 256) {
        int r = i >> 5, seg = i & 31;
        *(float4*)(Xs + r * HST + seg * 4) =
            ((const float4*)(X + list[r] * 128))[seg];
    }
    __syncthreads();

    // compute: warp job = 16 rows x 16 h (lane = 1 row x 8 h)
    const int rg  = wid >> 1;                    // 0..3 rowgroup
    const int row = rg * 16 + (lane & 15);
    const int h0  = (wid & 1) * 16 + (lane >> 4) * 8;
    if (rg * 16 >= cnt) return;

    ull a0 = 0, a1 = 0, a2 = 0, a3 = 0;
    const float* xr = Xs + row * HST;
#pragma unroll 4
    for (int d4 = 0; d4 < 32; d4++) {
        float4 x4 = *(const float4*)(xr + 4 * d4);
        const float* wp = Wsl + d4 * 128;        // 4 d-rows of 32
        float xs[4] = {x4.x, x4.y, x4.z, x4.w};
#pragma unroll
        for (int k = 0; k < 4; k++) {
            ull px = pack2(xs[k], xs[k]);
            ulonglong2 wA = *(const ulonglong2*)(wp + k * 32 + h0);
            ulonglong2 wB = *(const ulonglong2*)(wp + k * 32 + h0 + 4);
            a0 = fma2(px, wA.x, a0); a1 = fma2(px, wA.y, a1);
            a2 = fma2(px, wB.x, a2); a3 = fma2(px, wB.y, a3);
        }
    }
    if (row < cnt) {
        float* g = (side ? g_hd : g_hq) + ((size_t)(b * 64 + row) * 128) + hs4 * 32 + h0;
        float4 bA = *(const float4*)(b1s + h0);
        float4 bB = *(const float4*)(b1s + h0 + 4);
        float v0, v1, v2, v3;
        unpack2(a0, v0, v1); unpack2(a1, v2, v3);
        *(float4*)g = make_float4(v0 + bA.x, v1 + bA.y, v2 + bA.z, v3 + bA.w);
        unpack2(a2, v0, v1); unpack2(a3, v2, v3);
        *(float4*)(g + 4) = make_float4(v0 + bB.x, v1 + bB.y, v2 + bB.z, v3 + bB.w);
    }
}

// ============================================================================
// Pair: grid = 256 = (b, n-half, m-half). 256 threads, ~36KB smem, 6 blk/SM.
// Window-valid rows are a contiguous run of the full compacted list.
// ============================================================================
__global__ void __launch_bounds__(256)
pair_kernel(const void* __restrict__ qmask, const void* __restrict__ dmask,
            const float* __restrict__ W2g, const float* __restrict__ b2g,
            float* __restrict__ out)
{
    extern __shared__ float sm[];
    float* hq_s = sm;                   // [32][HST]
    float* hd_s = hq_s + 32 * HST;      // [32][HST]
    float* w2_s = hd_s + 32 * HST;      // [3][128]
    int* wnlist = (int*)(w2_s + 384);   // 33 (local n in window)
    int* wmlist = wnlist + 33;          // 33
    int* meta   = wmlist + 33;          // [0]=qstart [1]=qcnt [2]=mstart [3]=mcnt

    const int tid  = threadIdx.x;
    const int lane = tid & 31;
    const int wid  = tid >> 5;
    const int b    = blockIdx.x >> 2;
    const int nh   = (blockIdx.x >> 1) & 1;
    const int mh   = blockIdx.x & 1;

    // zero-fill own 32n x 32m x 3 window
    float* obase = out + (size_t)((b * 64 + nh * 32) * 64 + mh * 32) * 3;
    {
        float4 z = make_float4(0.f, 0.f, 0.f, 0.f);
        for (int i = tid; i < 768; i += 256) {
            int r = i / 24, c = i - r * 24;
            ((float4*)(obase + r * 192))[c] = z;
        }
    }

    if (wid == 0 || wid == 1) {
        const int mode = detect_mode(qmask, lane);
        const void* mp = (wid == 0) ? qmask : dmask;
        const int hh   = (wid == 0) ? nh : mh;
        int* wlist     = (wid == 0) ? wnlist : wmlist;
        const unsigned lt = (1u << lane) - 1u;
        bool v0 = mask_at(mp, b * 64 + lane, mode);
        unsigned m0 = __ballot_sync(0xFFFFFFFFu, v0);
        bool v1 = mask_at(mp, b * 64 + 32 + lane, mode);
        unsigned m1 = __ballot_sync(0xFFFFFFFFu, v1);
        unsigned win = hh ? m1 : m0;
        bool inwin = hh ? v1 : v0;
        if (inwin) wlist[__popc(win & lt)] = lane;
        if (lane == 0) {
            int c = __popc(win);
            meta[(wid == 0) ? 0 : 2] = hh ? __popc(m0) : 0;   // start
            meta[(wid == 0) ? 1 : 3] = c;                     // cnt
            if ((c & 1) && c) wlist[c] = 31 - __clz(win);     // pad dup of last
        }
    } else if (wid == 2 || wid == 3) {
        for (int i = tid - 64; i < 384; i += 64) {            // W2 -> [o][h]
            int h = i / 3, o = i - h * 3;
            w2_s[o * 128 + h] = W2g[i];
        }
    }
    __syncthreads();

    const int qstart = meta[0], qcnt = meta[1];
    const int mstart = meta[2], mcnt = meta[3];
    if (qcnt == 0 || mcnt == 0) return;
    const int qcp = (qcnt + 1) & ~1, mcp = (mcnt + 1) & ~1;

    // stage window hq/hd rows (pad row duplicates last valid)
    for (int i = tid; i < qcp * 32; i += 256) {
        int r = i >> 5, seg = i & 31;
        int j = qstart + min(r, qcnt - 1);
        *(float4*)(hq_s + r * HST + seg * 4) =
            ((const float4*)(g_hq + (size_t)(b * 64 + j) * 128))[seg];
    }
    for (int i = tid; i < mcp * 32; i += 256) {
        int r = i >> 5, seg = i & 31;
        int j = mstart + min(r, mcnt - 1);
        *(float4*)(hd_s + r * HST + seg * 4) =
            ((const float4*)(g_hd + (size_t)(b * 64 + j) * 128))[seg];
    }
    __syncthreads();

    // tiles: <=256, 1 per thread, rows paired (i, i+count/2)
    const int nt = qcp >> 1, mt = mcp >> 1;
    const int total = nt * mt;
    if (tid >= total) return;
    const int ni = tid / mt;
    const int mi = tid - ni * mt;
    const float* pa0 = hq_s + ni * HST;
    const float* pa1 = hq_s + (ni + nt) * HST;
    const float* pd0 = hd_s + mi * HST;
    const float* pd1 = hd_s + (mi + mt) * HST;
    const float b2_0 = b2g[0], b2_1 = b2g[1], b2_2 = b2g[2];

    ull acc[4][3];
#pragma unroll
    for (int c = 0; c < 4; c++)
#pragma unroll
        for (int o = 0; o < 3; o++) acc[c][o] = 0ull;

#define COMBO(c, Alo, Ahi, Dlo, Dhi) do {                                   \
        ull tlo = add2((Alo), (Dlo));                                        \
        ull thi = add2((Ahi), (Dhi));                                        \
        float f0, f1, f2, f3;                                                \
        unpack2(tlo, f0, f1); unpack2(thi, f2, f3);                          \
        f0 = fmaxf(f0, 0.f); f1 = fmaxf(f1, 0.f);                            \
        f2 = fmaxf(f2, 0.f); f3 = fmaxf(f3, 0.f);                            \
        tlo = pack2(f0, f1); thi = pack2(f2, f3);                            \
        acc[c][0] = fma2(tlo, w0.x, acc[c][0]);                              \
        acc[c][0] = fma2(thi, w0.y, acc[c][0]);                              \
        acc[c][1] = fma2(tlo, w1.x, acc[c][1]);                              \
        acc[c][1] = fma2(thi, w1.y, acc[c][1]);                              \
        acc[c][2] = fma2(tlo, w2v.x, acc[c][2]);                             \
        acc[c][2] = fma2(thi, w2v.y, acc[c][2]);                             \
    } while (0)

#pragma unroll 4
    for (int h = 0; h < 128; h += 4) {
        ulonglong2 A0 = *(const ulonglong2*)(pa0 + h);
        ulonglong2 A1 = *(const ulonglong2*)(pa1 + h);
        ulonglong2 D0 = *(const ulonglong2*)(pd0 + h);
        ulonglong2 D1 = *(const ulonglong2*)(pd1 + h);
        ulonglong2 w0  = *(const ulonglong2*)(w2_s + h);
        ulonglong2 w1  = *(const ulonglong2*)(w2_s + 128 + h);
        ulonglong2 w2v = *(const ulonglong2*)(w2_s + 256 + h);
        COMBO(0, A0.x, A0.y, D0.x, D0.y);
        COMBO(1, A0.x, A0.y, D1.x, D1.y);
        COMBO(2, A1.x, A1.y, D0.x, D0.y);
        COMBO(3, A1.x, A1.y, D1.x, D1.y);
    }
#undef COMBO

    const int gn0 = wnlist[ni], gn1 = wnlist[ni + nt];
    const int gm0 = wmlist[mi], gm1 = wmlist[mi + mt];

#define WRITE(c, gn, gm) do {                                               \
        float lo, hi, s0, s1, s2;                                            \
        unpack2(acc[c][0], lo, hi); s0 = lo + hi + b2_0;                     \
        unpack2(acc[c][1], lo, hi); s1 = lo + hi + b2_1;                     \
        unpack2(acc[c][2], lo, hi); s2 = lo + hi + b2_2;                     \
        float* po = obase + (gn) * 192 + (gm) * 3;                           \
        po[0] = s0; po[1] = s1; po[2] = s2;                                  \
    } while (0)

    WRITE(0, gn0, gm0);
    WRITE(1, gn0, gm1);
    WRITE(2, gn1, gm0);
    WRITE(3, gn1, gm1);
#undef WRITE
}

// ============================================================================
extern "C" void kernel_launch(void* const* d_in, const int* in_sizes, int n_in,
                              void* d_out, int out_size)
{
    const float* query = (const float*)d_in[0];
    const float* doc   = (const float*)d_in[1];
    const void*  qmask = d_in[2];
    const void*  dmask = d_in[3];
    const float* W1    = (const float*)d_in[4];
    const float* b1    = (const float*)d_in[5];
    const float* W2    = (const float*)d_in[6];
    const float* b2    = (const float*)d_in[7];
    float* out = (float*)d_out;

    const int sm1 = (128 * 32 + 64 * HST + 32) * (int)sizeof(float)
                    + (64 + 1) * (int)sizeof(int);             // ~50.6 KB
    const int sm2 = (32 * HST * 2 + 384) * (int)sizeof(float)
                    + (33 + 33 + 4) * (int)sizeof(int);        // ~35.6 KB

    cudaFuncSetAttribute(proj_kernel, cudaFuncAttributeMaxDynamicSharedMemorySize, sm1);
    cudaFuncSetAttribute(pair_kernel, cudaFuncAttributeMaxDynamicSharedMemorySize, sm2);

    proj_kernel<<<512, 256, sm1>>>(query, doc, qmask, dmask, W1, b1);
    pair_kernel<<<256, 256, sm2>>>(qmask, dmask, W2, b2, out);
}